// round 2
// baseline (speedup 1.0000x reference)
#include <cuda_runtime.h>
#include <cstdint>

#define DIMX 64
#define HIDX 128
#define BATCH 8192
#define NSTEPS 100
#define ROWS 64
#define NCTAS (BATCH / ROWS)
#define NTHREADS 256
#define DT_C 0.01f
#define SQDT_C 0.1f

// padded strides (all ≡ 4 mod 32 floats -> conflict-free fragment loads)
#define XS 68
#define HS 132
#define W1S 68
#define W2S 132

#define OFF_X 0
#define OFF_H (OFF_X + ROWS * XS)
#define OFF_WD1 (OFF_H + ROWS * HS)
#define OFF_WG1 (OFF_WD1 + HIDX * W1S)
#define OFF_WD2 (OFF_WG1 + HIDX * W1S)
#define OFF_WG2 (OFF_WD2 + DIMX * W2S)
#define OFF_BD1 (OFF_WG2 + DIMX * W2S)
#define OFF_BD2 (OFF_BD1 + HIDX)
#define OFF_BG1 (OFF_BD2 + DIMX)
#define OFF_BG2 (OFF_BG1 + HIDX)
#define SMEM_FLOATS (OFF_BG2 + DIMX)
#define SMEM_BYTES (SMEM_FLOATS * 4)

__device__ __forceinline__ uint32_t f2tf(float f) {
    uint32_t r;
    asm("cvt.rna.tf32.f32 %0, %1;" : "=r"(r) : "f"(f));
    return r;
}
__device__ __forceinline__ float tf32r(float f) {
    uint32_t r;
    asm("cvt.rna.tf32.f32 %0, %1;" : "=r"(r) : "f"(f));
    return __uint_as_float(r);
}
__device__ __forceinline__ void mma8(float* c, const uint32_t* a, const uint32_t* b) {
    asm volatile(
        "mma.sync.aligned.m16n8k8.row.col.f32.tf32.tf32.f32 "
        "{%0,%1,%2,%3},{%4,%5,%6,%7},{%8,%9},{%0,%1,%2,%3};\n"
        : "+f"(c[0]), "+f"(c[1]), "+f"(c[2]), "+f"(c[3])
        : "r"(a[0]), "r"(a[1]), "r"(a[2]), "r"(a[3]), "r"(b[0]), "r"(b[1]));
}
__device__ __forceinline__ float tanh_fast(float x) {
    // tanh(x) = 1 - 2/(e^{2x}+1); saturates correctly at +/-inf, ~1e-6 abs err
    float t = __expf(2.0f * x);
    return 1.0f - __fdividef(2.0f, t + 1.0f);
}

// h = tanh(x @ W1 + b1), stored tf32-rounded into smem h
// warp tile: 2 M-tiles (32 rows) x 4 N-tiles (32 cols)
__device__ __forceinline__ void phaseA(const float* __restrict__ sx,
                                       const float* __restrict__ w1,
                                       const float* __restrict__ b1,
                                       float* __restrict__ h,
                                       int mh, int nq, int g, int tg) {
    float c[2][4][4];
#pragma unroll
    for (int m = 0; m < 2; m++)
#pragma unroll
        for (int n = 0; n < 4; n++)
#pragma unroll
            for (int j = 0; j < 4; j++) c[m][n][j] = 0.f;

    const int r0 = 32 * mh, c0 = 32 * nq;
#pragma unroll 2
    for (int k8 = 0; k8 < DIMX; k8 += 8) {
        uint32_t a[2][4];
#pragma unroll
        for (int m = 0; m < 2; m++) {
            const float* xp = sx + (r0 + 16 * m + g) * XS + k8 + tg;
            a[m][0] = f2tf(xp[0]);
            a[m][1] = f2tf(xp[8 * XS]);
            a[m][2] = f2tf(xp[4]);
            a[m][3] = f2tf(xp[8 * XS + 4]);
        }
#pragma unroll
        for (int n = 0; n < 4; n++) {
            const float* wp = w1 + (c0 + 8 * n + g) * W1S + k8 + tg;
            uint32_t b[2] = {__float_as_uint(wp[0]), __float_as_uint(wp[4])};
            mma8(c[0][n], a[0], b);
            mma8(c[1][n], a[1], b);
        }
    }
#pragma unroll
    for (int m = 0; m < 2; m++)
#pragma unroll
        for (int n = 0; n < 4; n++) {
            int rr = r0 + 16 * m + g, cc = c0 + 8 * n + 2 * tg;
            float bb0 = b1[cc], bb1 = b1[cc + 1];
            float2 v0, v1;
            v0.x = tf32r(tanh_fast(c[m][n][0] + bb0));
            v0.y = tf32r(tanh_fast(c[m][n][1] + bb1));
            v1.x = tf32r(tanh_fast(c[m][n][2] + bb0));
            v1.y = tf32r(tanh_fast(c[m][n][3] + bb1));
            *(float2*)(h + rr * HS + cc) = v0;
            *(float2*)(h + (rr + 8) * HS + cc) = v1;
        }
}

// c[16] += h @ W2 for warp tile: 1 M-tile (16 rows) x 4 N-tiles (32 cols)
__device__ __forceinline__ void phaseB(const float* __restrict__ h,
                                       const float* __restrict__ w2,
                                       float* __restrict__ c,
                                       int mt, int nh, int g, int tg) {
#pragma unroll
    for (int j = 0; j < 16; j++) c[j] = 0.f;
    const int r0 = 16 * mt, c0 = 32 * nh;
#pragma unroll 2
    for (int k8 = 0; k8 < HIDX; k8 += 8) {
        const float* hp = h + (r0 + g) * HS + k8 + tg;
        uint32_t a[4] = {__float_as_uint(hp[0]), __float_as_uint(hp[8 * HS]),
                         __float_as_uint(hp[4]), __float_as_uint(hp[8 * HS + 4])};
#pragma unroll
        for (int n = 0; n < 4; n++) {
            const float* wp = w2 + (c0 + 8 * n + g) * W2S + k8 + tg;
            uint32_t b[2] = {__float_as_uint(wp[0]), __float_as_uint(wp[4])};
            mma8(c + 4 * n, a, b);
        }
    }
}

__global__ void __launch_bounds__(NTHREADS, 1) sde_kernel(
    const float* __restrict__ x0, const float* __restrict__ noise,
    const float* __restrict__ Wd1, const float* __restrict__ bd1,
    const float* __restrict__ Wd2, const float* __restrict__ bd2,
    const float* __restrict__ Wg1, const float* __restrict__ bg1,
    const float* __restrict__ Wg2, const float* __restrict__ bg2,
    float* __restrict__ out) {
    extern __shared__ float sm[];
    const int tid = threadIdx.x;
    const int rowBase = blockIdx.x * ROWS;

    // Load weights transposed to [n][k], tf32-rounded once.
    for (int i = tid; i < DIMX * HIDX; i += NTHREADS) {
        int k = i / HIDX, n = i % HIDX;  // W1 is [DIM][HID]
        sm[OFF_WD1 + n * W1S + k] = tf32r(Wd1[i]);
        sm[OFF_WG1 + n * W1S + k] = tf32r(Wg1[i]);
        int k2 = i / DIMX, n2 = i % DIMX;  // W2 is [HID][DIM]
        sm[OFF_WD2 + n2 * W2S + k2] = tf32r(Wd2[i]);
        sm[OFF_WG2 + n2 * W2S + k2] = tf32r(Wg2[i]);
    }
    for (int i = tid; i < HIDX; i += NTHREADS) {
        sm[OFF_BD1 + i] = bd1[i];
        sm[OFF_BG1 + i] = bg1[i];
    }
    for (int i = tid; i < DIMX; i += NTHREADS) {
        sm[OFF_BD2 + i] = bd2[i];
        sm[OFF_BG2 + i] = bg2[i];
    }
    // x0 into smem (full fp32 state) and out[0]
    for (int i = tid; i < ROWS * DIMX; i += NTHREADS) {
        int r = i / DIMX, c = i % DIMX;
        float v = x0[(rowBase + r) * DIMX + c];
        sm[OFF_X + r * XS + c] = v;
        out[(rowBase + r) * DIMX + c] = v;
    }
    __syncthreads();

    const int warp = tid >> 5, lane = tid & 31, g = lane >> 2, tg = lane & 3;
    const int a_mh = warp & 1, a_nq = warp >> 1;  // phase A tile map
    const int b_mt = warp & 3, b_nh = warp >> 2;  // phase B tile map

    float fc[16];

#pragma unroll 1
    for (int step = 0; step < NSTEPS; ++step) {
        // drift MLP
        phaseA(sm + OFF_X, sm + OFF_WD1, sm + OFF_BD1, sm + OFF_H, a_mh, a_nq, g, tg);
        __syncthreads();
        phaseB(sm + OFF_H, sm + OFF_WD2, fc, b_mt, b_nh, g, tg);
        __syncthreads();  // h about to be overwritten
        // diffusion MLP
        phaseA(sm + OFF_X, sm + OFF_WG1, sm + OFF_BG1, sm + OFF_H, a_mh, a_nq, g, tg);
        __syncthreads();
        float gc[16];
        phaseB(sm + OFF_H, sm + OFF_WG2, gc, b_mt, b_nh, g, tg);

        // combine: x += (f+bd2)*dt + (g+bg2)*dw*sqrt(dt); each element single-owner
        {
            const int r0 = 16 * b_mt + g;
            const float* nz = noise + ((size_t)step * BATCH + rowBase) * DIMX;
            float* op = out + ((size_t)(step + 1) * BATCH + rowBase) * DIMX;
#pragma unroll
            for (int n = 0; n < 4; n++) {
                int cc = 32 * b_nh + 8 * n + 2 * tg;
                float bd0 = sm[OFF_BD2 + cc], bd1v = sm[OFF_BD2 + cc + 1];
                float bg0 = sm[OFF_BG2 + cc], bg1v = sm[OFF_BG2 + cc + 1];
#pragma unroll
                for (int h2 = 0; h2 < 2; h2++) {
                    int rr = r0 + 8 * h2;
                    float2 dw = *(const float2*)(nz + rr * DIMX + cc);
                    float* xp = sm + OFF_X + rr * XS + cc;
                    float xnx = xp[0] + (fc[4 * n + 2 * h2 + 0] + bd0) * DT_C +
                                (gc[4 * n + 2 * h2 + 0] + bg0) * (dw.x * SQDT_C);
                    float xny = xp[1] + (fc[4 * n + 2 * h2 + 1] + bd1v) * DT_C +
                                (gc[4 * n + 2 * h2 + 1] + bg1v) * (dw.y * SQDT_C);
                    xp[0] = xnx;
                    xp[1] = xny;
                    *(float2*)(op + rr * DIMX + cc) = make_float2(xnx, xny);
                }
            }
        }
        __syncthreads();  // x ready for next step
    }
}

extern "C" void kernel_launch(void* const* d_in, const int* in_sizes, int n_in,
                              void* d_out, int out_size) {
    (void)in_sizes; (void)n_in; (void)out_size;
    const float* x0 = (const float*)d_in[0];
    // d_in[1] = t_span (unused)
    const float* noise = (const float*)d_in[2];
    const float* Wd1 = (const float*)d_in[3];
    const float* bd1 = (const float*)d_in[4];
    const float* Wd2 = (const float*)d_in[5];
    const float* bd2 = (const float*)d_in[6];
    const float* Wg1 = (const float*)d_in[7];
    const float* bg1 = (const float*)d_in[8];
    const float* Wg2 = (const float*)d_in[9];
    const float* bg2 = (const float*)d_in[10];
    float* out = (float*)d_out;

    cudaFuncSetAttribute(sde_kernel, cudaFuncAttributeMaxDynamicSharedMemorySize, SMEM_BYTES);
    sde_kernel<<<NCTAS, NTHREADS, SMEM_BYTES>>>(x0, noise, Wd1, bd1, Wd2, bd2,
                                                Wg1, bg1, Wg2, bg2, out);
}

// round 3
// speedup vs baseline: 1.1004x; 1.1004x over previous
#include <cuda_runtime.h>
#include <cstdint>

#define DIMX 64
#define HIDX 128
#define BATCH 8192
#define NSTEPS 100
#define ROWS 64
#define NCTAS 128
#define NTHREADS 256
#define DT_C 0.01f
#define SQDT_C 0.1f

// ── smem float offsets ──────────────────────────────────────────────
// X: 64x64 tf32 x (pair-permuted + swizzled). Dead between S1 and S5,
//    so it doubles as the f-buffer (same element->address mapping).
#define OFF_X   0
#define OFF_HD  4096     // h_drift 64x128 (perm+swz)
#define OFF_HG  12288    // h_diff  64x128
#define OFF_W1D 20480    // W1d^T: 128 rows x 64 (perm+swz)
#define OFF_W1G 28672
#define OFF_W2D 36864    // W2d^T: 64 rows x 128
#define OFF_W2G 45056
#define OFF_NZ  53248    // noise 64x64 (swz only, no perm)
#define OFF_B1D 57344
#define OFF_B1G 57472
#define OFF_B2D 57600
#define OFF_B2G 57664
#define SMEM_FLOATS 57728
#define SMEM_BYTES (SMEM_FLOATS * 4)

// position of element k inside its row: pairs (k, k+4) stored adjacent
__device__ __forceinline__ int permpos(int k) {
    return ((k >> 3) << 3) + 2 * (k & 3) + ((k >> 2) & 1);
}
__device__ __forceinline__ float tf32r(float f) {
    uint32_t r;
    asm("cvt.rna.tf32.f32 %0, %1;" : "=r"(r) : "f"(f));
    return __uint_as_float(r);
}
__device__ __forceinline__ void mma8(float* c, uint32_t a0, uint32_t a1,
                                     uint32_t a2, uint32_t a3, uint32_t b0,
                                     uint32_t b1) {
    asm volatile(
        "mma.sync.aligned.m16n8k8.row.col.f32.tf32.tf32.f32 "
        "{%0,%1,%2,%3},{%4,%5,%6,%7},{%8,%9},{%0,%1,%2,%3};\n"
        : "+f"(c[0]), "+f"(c[1]), "+f"(c[2]), "+f"(c[3])
        : "r"(a0), "r"(a1), "r"(a2), "r"(a3), "r"(b0), "r"(b1));
}
__device__ __forceinline__ float tanh_fast(float x) {
    float t = __expf(2.0f * x);
    return 1.0f - __fdividef(2.0f, t + 1.0f);
}

__global__ void __launch_bounds__(NTHREADS, 1) sde_kernel(
    const float* __restrict__ x0, const float* __restrict__ noise,
    const float* __restrict__ Wd1, const float* __restrict__ bd1,
    const float* __restrict__ Wd2, const float* __restrict__ bd2,
    const float* __restrict__ Wg1, const float* __restrict__ bg1,
    const float* __restrict__ Wg2, const float* __restrict__ bg2,
    float* __restrict__ out) {
    extern __shared__ float sm[];
    const int tid = threadIdx.x;
    const int warp = tid >> 5, lane = tid & 31, g = lane >> 2, tg = lane & 3;
    const int rowBase = blockIdx.x * ROWS;
    const int sw = 8 * (g & 3);  // all rows a lane touches have row&3 == g&3

    // ── init: weights (tf32, transposed, perm+swz) ──────────────────
    for (int i = tid; i < DIMX * HIDX; i += NTHREADS) {
        int k = i >> 7, n = i & 127;  // W1[k][n]
        int p = permpos(k) ^ (8 * (n & 3));
        sm[OFF_W1D + n * 64 + p] = tf32r(Wd1[i]);
        sm[OFF_W1G + n * 64 + p] = tf32r(Wg1[i]);
        int k2 = i >> 6, n2 = i & 63;  // W2[k2][n2]
        int p2 = permpos(k2) ^ (8 * (n2 & 3));
        sm[OFF_W2D + n2 * 128 + p2] = tf32r(Wd2[i]);
        sm[OFF_W2G + n2 * 128 + p2] = tf32r(Wg2[i]);
    }
    for (int i = tid; i < HIDX; i += NTHREADS) {
        sm[OFF_B1D + i] = bd1[i];
        sm[OFF_B1G + i] = bg1[i];
    }
    for (int i = tid; i < DIMX; i += NTHREADS) {
        sm[OFF_B2D + i] = bd2[i];
        sm[OFF_B2G + i] = bg2[i];
    }
    // x0 -> smem (tf32 copy) + out[0]
    for (int i = tid; i < ROWS * DIMX; i += NTHREADS) {
        int r = i >> 6, c = i & 63;
        float v = x0[(rowBase + r) * DIMX + c];
        sm[OFF_X + r * 64 + (permpos(c) ^ (8 * (r & 3)))] = tf32r(v);
        out[(rowBase + r) * DIMX + c] = v;
    }

    // phase A tile: rows 32*(warp&1), cols 32*(warp>>1)  (all 8 warps)
    const int aR = 32 * (warp & 1), aC = 32 * (warp >> 1);
    // phase B tile: idx = warp&3 -> rows 32*(idx&1), cols 32*(idx>>1)
    const int bR = 32 * ((warp & 3) & 1), bC = 32 * ((warp & 3) >> 1);
    const bool isDrift = warp < 4;

    // fp32 x state in registers (diffusion warps own all 64x64 elements)
    float2 xr[2][4][2];
    if (!isDrift) {
#pragma unroll
        for (int m = 0; m < 2; m++)
#pragma unroll
            for (int n = 0; n < 4; n++)
#pragma unroll
                for (int h = 0; h < 2; h++) {
                    int row = bR + 16 * m + 8 * h + g;
                    int cc = bC + 8 * n + 2 * tg;
                    xr[m][n][h] =
                        *(const float2*)(x0 + (rowBase + row) * DIMX + cc);
                }
    }

    uint32_t smb;
    asm("{.reg .u64 t; cvta.to.shared.u64 t, %1; cvt.u32.u64 %0, t;}"
        : "=r"(smb) : "l"(sm));
    __syncthreads();

#pragma unroll 1
    for (int step = 0; step < NSTEPS; ++step) {
        // ── noise prefetch (drift warps, cp.async) ──────────────────
        if (isDrift) {
            const float* nzg = noise + ((size_t)step * BATCH + rowBase) * DIMX;
#pragma unroll
            for (int j = 0; j < 8; j++) {
                int chunk = j * 128 + tid;  // 1024 16B chunks
                int r = chunk >> 4, c4 = (chunk & 15) * 4;
                uint32_t dst = smb + (OFF_NZ + r * 64 + (c4 ^ (8 * (r & 3)))) * 4;
                asm volatile("cp.async.ca.shared.global [%0], [%1], 16;\n" ::
                                 "r"(dst), "l"(nzg + r * 64 + c4));
            }
            asm volatile("cp.async.commit_group;\n");
        }

        // ── phase A fused: h_d = tanh(xW1d+b), h_g = tanh(xW1g+b) ───
        {
            float cd[2][4][4] = {}, cg[2][4][4] = {};
#pragma unroll
            for (int k8 = 0; k8 < 8; k8++) {
                const int ko = (k8 * 8 + 2 * tg) ^ sw;
                uint2 a[2][2];
#pragma unroll
                for (int m = 0; m < 2; m++) {
                    int r0 = aR + 16 * m + g;
                    a[m][0] = *(const uint2*)(sm + OFF_X + r0 * 64 + ko);
                    a[m][1] = *(const uint2*)(sm + OFF_X + (r0 + 8) * 64 + ko);
                }
#pragma unroll
                for (int n = 0; n < 4; n++) {
                    int wr = aC + 8 * n + g;
                    uint2 bd_ = *(const uint2*)(sm + OFF_W1D + wr * 64 + ko);
                    uint2 bg_ = *(const uint2*)(sm + OFF_W1G + wr * 64 + ko);
#pragma unroll
                    for (int m = 0; m < 2; m++) {
                        mma8(cd[m][n], a[m][0].x, a[m][1].x, a[m][0].y,
                             a[m][1].y, bd_.x, bd_.y);
                        mma8(cg[m][n], a[m][0].x, a[m][1].x, a[m][0].y,
                             a[m][1].y, bg_.x, bg_.y);
                    }
                }
            }
#pragma unroll
            for (int m = 0; m < 2; m++) {
                int r0 = aR + 16 * m + g;
#pragma unroll
                for (int n = 0; n < 4; n++) {
                    int cc = aC + 8 * n + 2 * tg;
                    int p0 = permpos(cc) ^ sw, p1 = permpos(cc + 1) ^ sw;
                    float d0 = sm[OFF_B1D + cc], d1 = sm[OFF_B1D + cc + 1];
                    float e0 = sm[OFF_B1G + cc], e1 = sm[OFF_B1G + cc + 1];
                    sm[OFF_HD + r0 * 128 + p0] = tf32r(tanh_fast(cd[m][n][0] + d0));
                    sm[OFF_HD + r0 * 128 + p1] = tf32r(tanh_fast(cd[m][n][1] + d1));
                    sm[OFF_HD + (r0 + 8) * 128 + p0] = tf32r(tanh_fast(cd[m][n][2] + d0));
                    sm[OFF_HD + (r0 + 8) * 128 + p1] = tf32r(tanh_fast(cd[m][n][3] + d1));
                    sm[OFF_HG + r0 * 128 + p0] = tf32r(tanh_fast(cg[m][n][0] + e0));
                    sm[OFF_HG + r0 * 128 + p1] = tf32r(tanh_fast(cg[m][n][1] + e1));
                    sm[OFF_HG + (r0 + 8) * 128 + p0] = tf32r(tanh_fast(cg[m][n][2] + e0));
                    sm[OFF_HG + (r0 + 8) * 128 + p1] = tf32r(tanh_fast(cg[m][n][3] + e1));
                }
            }
        }
        __syncthreads();  // S1: h ready

        // ── phase B split: warps 0-3 -> f (drift), 4-7 -> g (diff) ──
        float c[2][4][4] = {};
        {
            const float* hb = sm + (isDrift ? OFF_HD : OFF_HG);
            const float* wb = sm + (isDrift ? OFF_W2D : OFF_W2G);
#pragma unroll
            for (int k8 = 0; k8 < 16; k8++) {
                const int ko = (k8 * 8 + 2 * tg) ^ sw;
                uint2 a[2][2];
#pragma unroll
                for (int m = 0; m < 2; m++) {
                    int r0 = bR + 16 * m + g;
                    a[m][0] = *(const uint2*)(hb + r0 * 128 + ko);
                    a[m][1] = *(const uint2*)(hb + (r0 + 8) * 128 + ko);
                }
#pragma unroll
                for (int n = 0; n < 4; n++) {
                    int wr = bC + 8 * n + g;
                    uint2 b_ = *(const uint2*)(wb + wr * 128 + ko);
#pragma unroll
                    for (int m = 0; m < 2; m++)
                        mma8(c[m][n], a[m][0].x, a[m][1].x, a[m][0].y,
                             a[m][1].y, b_.x, b_.y);
                }
            }
        }
        if (isDrift) {
            // f (+bd2) -> X region (x's tf32 copy is dead until S2+)
#pragma unroll
            for (int m = 0; m < 2; m++) {
                int r0 = bR + 16 * m + g;
#pragma unroll
                for (int n = 0; n < 4; n++) {
                    int cc = bC + 8 * n + 2 * tg;
                    int p0 = permpos(cc) ^ sw, p1 = permpos(cc + 1) ^ sw;
                    float d0 = sm[OFF_B2D + cc], d1 = sm[OFF_B2D + cc + 1];
                    sm[OFF_X + r0 * 64 + p0] = c[m][n][0] + d0;
                    sm[OFF_X + r0 * 64 + p1] = c[m][n][1] + d1;
                    sm[OFF_X + (r0 + 8) * 64 + p0] = c[m][n][2] + d0;
                    sm[OFF_X + (r0 + 8) * 64 + p1] = c[m][n][3] + d1;
                }
            }
            asm volatile("cp.async.wait_group 0;\n");
        }
        __syncthreads();  // S2: f + noise ready

        if (!isDrift) {
            // combine: x += (f)*dt + (g+bg2)*dw*sqrt(dt); refresh smem x
            float* op = out + ((size_t)(step + 1) * BATCH + rowBase) * DIMX;
#pragma unroll
            for (int m = 0; m < 2; m++) {
#pragma unroll
                for (int n = 0; n < 4; n++) {
                    int cc = bC + 8 * n + 2 * tg;
                    int p0 = permpos(cc) ^ sw, p1 = permpos(cc + 1) ^ sw;
                    float e0 = sm[OFF_B2G + cc], e1 = sm[OFF_B2G + cc + 1];
#pragma unroll
                    for (int h = 0; h < 2; h++) {
                        int row = bR + 16 * m + 8 * h + g;
                        float2 nz = *(const float2*)(sm + OFF_NZ + row * 64 +
                                                     (cc ^ sw));
                        float f0 = sm[OFF_X + row * 64 + p0];
                        float f1 = sm[OFF_X + row * 64 + p1];
                        float g0 = c[m][n][2 * h + 0] + e0;
                        float g1 = c[m][n][2 * h + 1] + e1;
                        float xn0 = xr[m][n][h].x + f0 * DT_C + g0 * (nz.x * SQDT_C);
                        float xn1 = xr[m][n][h].y + f1 * DT_C + g1 * (nz.y * SQDT_C);
                        xr[m][n][h] = make_float2(xn0, xn1);
                        sm[OFF_X + row * 64 + p0] = tf32r(xn0);
                        sm[OFF_X + row * 64 + p1] = tf32r(xn1);
                        *(float2*)(op + row * 64 + cc) = make_float2(xn0, xn1);
                    }
                }
            }
        }
        __syncthreads();  // S3: x ready for next step
    }
}

extern "C" void kernel_launch(void* const* d_in, const int* in_sizes, int n_in,
                              void* d_out, int out_size) {
    (void)in_sizes; (void)n_in; (void)out_size;
    const float* x0 = (const float*)d_in[0];
    // d_in[1] = t_span (unused)
    const float* noise = (const float*)d_in[2];
    const float* Wd1 = (const float*)d_in[3];
    const float* bd1 = (const float*)d_in[4];
    const float* Wd2 = (const float*)d_in[5];
    const float* bd2 = (const float*)d_in[6];
    const float* Wg1 = (const float*)d_in[7];
    const float* bg1 = (const float*)d_in[8];
    const float* Wg2 = (const float*)d_in[9];
    const float* bg2 = (const float*)d_in[10];
    float* out = (float*)d_out;

    cudaFuncSetAttribute(sde_kernel, cudaFuncAttributeMaxDynamicSharedMemorySize,
                         SMEM_BYTES);
    sde_kernel<<<NCTAS, NTHREADS, SMEM_BYTES>>>(x0, noise, Wd1, bd1, Wd2, bd2,
                                                Wg1, bg1, Wg2, bg2, out);
}